// round 12
// baseline (speedup 1.0000x reference)
#include <cuda_runtime.h>

#define NB 8
#define NP 4096
#define NS 1024

// ---------------- device scratch (static: no allocation allowed) ----------------
__device__ float gPQ0[NB*NP*32];
__device__ float gPQ1[NB*NP*64];
__device__ float gPQ2[NB*NP*64];
__device__ int   gIdx0[NB*NS*16];
__device__ int   gIdx1[NB*NS*32];
__device__ int   gIdx2[NB*NS*128];

// packed fp32x2 FMA (sm_100+): 2 MACs/instr
__device__ __forceinline__ float2 ffma2(float2 a, float2 b, float2 c){
    unsigned long long au, bu, cu, du;
    au = *reinterpret_cast<const unsigned long long*>(&a);
    bu = *reinterpret_cast<const unsigned long long*>(&b);
    cu = *reinterpret_cast<const unsigned long long*>(&c);
    asm("fma.rn.f32x2 %0, %1, %2, %3;" : "=l"(du) : "l"(au), "l"(bu), "l"(cu));
    return *reinterpret_cast<float2*>(&du);
}
__device__ __forceinline__ float2 f2lo(float4 v){ return make_float2(v.x, v.y); }
__device__ __forceinline__ float2 f2hi(float4 v){ return make_float2(v.z, v.w); }

// per-lane weight column in registers; h-row read is warp-uniform (broadcast LDS)
template<int CIN>
__device__ __forceinline__ void load_w(float4* wr, const float* __restrict__ w, int col){
    const float4* wp = reinterpret_cast<const float4*>(w + (size_t)col*CIN);
#pragma unroll
    for (int i = 0; i < CIN/4; i++) wr[i] = wp[i];
}
template<int CIN>
__device__ __forceinline__ float dotrow(const float* __restrict__ h, const float4* wr){
    float2 a0 = make_float2(0.f,0.f), a1 = make_float2(0.f,0.f);
#pragma unroll
    for (int i = 0; i < CIN/8; i++){
        float4 ha = *reinterpret_cast<const float4*>(h + 8*i);
        float4 hb = *reinterpret_cast<const float4*>(h + 8*i + 4);
        a0 = ffma2(f2lo(ha), f2lo(wr[2*i]),   a0);
        a0 = ffma2(f2hi(ha), f2hi(wr[2*i]),   a0);
        a1 = ffma2(f2lo(hb), f2lo(wr[2*i+1]), a1);
        a1 = ffma2(f2hi(hb), f2hi(wr[2*i+1]), a1);
    }
    return (a0.x + a0.y) + (a1.x + a1.y);
}

// ---------------- FPS (unchanged, passing) ----------------
__global__ void __launch_bounds__(1024) fps_kernel(
    const float* __restrict__ xyz, float* __restrict__ newxyz)
{
    extern __shared__ float sfm[];
    __shared__ unsigned long long swarp[32];
    __shared__ float scent[3];
    float* sx = sfm; float* sy = sfm + NP; float* sz = sfm + 2*NP;

    const int b = blockIdx.x, tid = threadIdx.x;
    const float* xb = xyz + (size_t)b * NP * 3;

    float px[4], py[4], pz[4], dist[4];
#pragma unroll
    for (int i = 0; i < 4; i++){
        int p = tid + 1024*i;
        px[i] = xb[3*p]; py[i] = xb[3*p+1]; pz[i] = xb[3*p+2];
        sx[p] = px[i]; sy[p] = py[i]; sz[p] = pz[i];
        dist[i] = 1e10f;
    }
    if (tid == 0){ scent[0] = px[0]; scent[1] = py[0]; scent[2] = pz[0]; }
    __syncthreads();

    for (int it = 0; it < NS; ++it){
        const float cx = scent[0], cy = scent[1], cz = scent[2];
        if (tid == 0){
            float* o = newxyz + ((size_t)b * NS + it) * 3;
            o[0] = cx; o[1] = cy; o[2] = cz;
        }
        float m; unsigned mi;
#pragma unroll
        for (int i = 0; i < 4; i++){
            float dx = px[i]-cx, dy = py[i]-cy, dz = pz[i]-cz;
            float d = __fadd_rn(__fadd_rn(__fmul_rn(dx,dx), __fmul_rn(dy,dy)), __fmul_rn(dz,dz));
            float nd = fminf(dist[i], d);
            dist[i] = nd;
            if (i == 0){ m = nd; mi = (unsigned)tid; }
            else if (nd > m){ m = nd; mi = (unsigned)(tid + 1024*i); }
        }
        unsigned long long best = ((unsigned long long)__float_as_uint(m) << 32)
                                | (unsigned long long)(0xFFFFFFFFu - mi);
#pragma unroll
        for (int off = 16; off; off >>= 1){
            unsigned long long o = __shfl_down_sync(0xFFFFFFFFu, best, off);
            if (o > best) best = o;
        }
        if ((tid & 31) == 0) swarp[tid >> 5] = best;
        __syncthreads();
        if (tid < 32){
            unsigned long long v = swarp[tid];
#pragma unroll
            for (int off = 16; off; off >>= 1){
                unsigned long long o = __shfl_down_sync(0xFFFFFFFFu, v, off);
                if (o > v) v = o;
            }
            if (tid == 0){
                unsigned w = 0xFFFFFFFFu - (unsigned)(v & 0xFFFFFFFFull);
                scent[0] = sx[w]; scent[1] = sy[w]; scent[2] = sz[w];
            }
        }
        __syncthreads();
    }
}

// ---------------- PQ precompute (unchanged, passing) ----------------
__global__ void __launch_bounds__(160) pq_kernel(
    const float* __restrict__ xyz, const float* __restrict__ feat,
    const float* __restrict__ w00, const float* __restrict__ b00,
    const float* __restrict__ w10, const float* __restrict__ b10,
    const float* __restrict__ w20, const float* __restrict__ b20)
{
    __shared__ float sin_[8*68];
    const int tid = threadIdx.x;
    const float* wrow; float bias; float* dst; int C, ch;
    if (tid < 32)      { wrow = w00 + tid*67;      bias = b00[tid];    dst = gPQ0; C = 32; ch = tid; }
    else if (tid < 96) { wrow = w10 + (tid-32)*67; bias = b10[tid-32]; dst = gPQ1; C = 64; ch = tid-32; }
    else               { wrow = w20 + (tid-96)*67; bias = b20[tid-96]; dst = gPQ2; C = 64; ch = tid-96; }
    float wreg[67];
#pragma unroll
    for (int i = 0; i < 67; i++) wreg[i] = wrow[i];

    for (int grp = 0; grp < 4; grp++){
        int gbase = blockIdx.x * 32 + grp * 8;
        __syncthreads();
        for (int t = tid; t < 8*67; t += 160){
            int pt = t / 67, c = t - 67*pt;
            int g = gbase + pt;
            sin_[pt*68 + c] = (c < 3) ? xyz[(size_t)g*3 + c] : feat[(size_t)g*64 + (c-3)];
        }
        __syncthreads();
#pragma unroll 1
        for (int pt = 0; pt < 8; pt++){
            const float* inp = &sin_[pt*68];
            float a0 = bias, a1 = 0.f;
#pragma unroll
            for (int i = 0; i < 8; i++){
                float4 v0 = *reinterpret_cast<const float4*>(inp + 8*i);
                float4 v1 = *reinterpret_cast<const float4*>(inp + 8*i + 4);
                a0 = fmaf(v0.x, wreg[8*i+0], a0); a0 = fmaf(v0.y, wreg[8*i+1], a0);
                a0 = fmaf(v0.z, wreg[8*i+2], a0); a0 = fmaf(v0.w, wreg[8*i+3], a0);
                a1 = fmaf(v1.x, wreg[8*i+4], a1); a1 = fmaf(v1.y, wreg[8*i+5], a1);
                a1 = fmaf(v1.z, wreg[8*i+6], a1); a1 = fmaf(v1.w, wreg[8*i+7], a1);
            }
            a0 = fmaf(inp[64], wreg[64], a0);
            a1 = fmaf(inp[65], wreg[65], a1);
            a0 = fmaf(inp[66], wreg[66], a0);
            dst[(size_t)(gbase + pt) * C + ch] = a0 + a1;
        }
    }
}

// ---------------- ball query (unchanged, passing) ----------------
__global__ void __launch_bounds__(128) ball_kernel(
    const float* __restrict__ xyz, const float* __restrict__ newxyz)
{
    const int bs = blockIdx.x;
    const int b = bs >> 10;
    const int tid = threadIdx.x;
    const int w = tid >> 5, lane = tid & 31;
    const float cx = newxyz[(size_t)bs*3+0];
    const float cy = newxyz[(size_t)bs*3+1];
    const float cz = newxyz[(size_t)bs*3+2];
    const float nn = __fadd_rn(__fadd_rn(__fmul_rn(cx,cx), __fmul_rn(cy,cy)), __fmul_rn(cz,cz));
    __shared__ int cnt[3], wcnt[3][4], sfirst[3];
    if (tid < 3){ cnt[tid] = 0; sfirst[tid] = 0; }
    __syncthreads();
    const float* xb = xyz + (size_t)b * NP * 3;

    for (int jb = 0; jb < NP; jb += 128){
        int j = jb + tid;
        float x = xb[3*j], y = xb[3*j+1], z = xb[3*j+2];
        float pp  = __fadd_rn(__fadd_rn(__fmul_rn(x,x), __fmul_rn(y,y)), __fmul_rn(z,z));
        float dot = __fadd_rn(__fadd_rn(__fmul_rn(cx,x), __fmul_rn(cy,y)), __fmul_rn(cz,z));
        float sqd = __fsub_rn(__fadd_rn(nn, pp), __fmul_rn(2.0f, dot));
        bool in0 = !(sqd > 0.01f);
        bool in1 = !(sqd > 0.04f);
        bool in2 = !(sqd > 0.16f);
        unsigned m0 = __ballot_sync(0xFFFFFFFFu, in0);
        unsigned m1 = __ballot_sync(0xFFFFFFFFu, in1);
        unsigned m2 = __ballot_sync(0xFFFFFFFFu, in2);
        if (lane == 0){ wcnt[0][w]=__popc(m0); wcnt[1][w]=__popc(m1); wcnt[2][w]=__popc(m2); }
        __syncthreads();
        unsigned lm = (1u << lane) - 1u;
        int b0 = cnt[0], b1 = cnt[1], b2 = cnt[2];
        for (int ww = 0; ww < w; ww++){ b0 += wcnt[0][ww]; b1 += wcnt[1][ww]; b2 += wcnt[2][ww]; }
        if (in0){ int p = b0 + __popc(m0 & lm); if (p == 0) sfirst[0] = j; if (p < 16)  gIdx0[(size_t)bs*16  + p] = j; }
        if (in1){ int p = b1 + __popc(m1 & lm); if (p == 0) sfirst[1] = j; if (p < 32)  gIdx1[(size_t)bs*32  + p] = j; }
        if (in2){ int p = b2 + __popc(m2 & lm); if (p == 0) sfirst[2] = j; if (p < 128) gIdx2[(size_t)bs*128 + p] = j; }
        __syncthreads();
        if (tid == 0){
            cnt[0] += wcnt[0][0]+wcnt[0][1]+wcnt[0][2]+wcnt[0][3];
            cnt[1] += wcnt[1][0]+wcnt[1][1]+wcnt[1][2]+wcnt[1][3];
            cnt[2] += wcnt[2][0]+wcnt[2][1]+wcnt[2][2]+wcnt[2][3];
        }
        __syncthreads();
        if (cnt[0] >= 16 && cnt[1] >= 32 && cnt[2] >= 128) break;
    }
    int f0 = sfirst[0], f1 = sfirst[1], f2 = sfirst[2];
    for (int q = cnt[0] + tid; q < 16;  q += 128) gIdx0[(size_t)bs*16  + q] = f0;
    for (int q = cnt[1] + tid; q < 32;  q += 128) gIdx1[(size_t)bs*32  + q] = f1;
    for (int q = cnt[2] + tid; q < 128; q += 128) gIdx2[(size_t)bs*128 + q] = f2;
}

// ---------------- MLP: lane=column (weights in regs), rows broadcast from smem ----------------
template<int SCALE,int BC,int K,int C1,int C2,int C3,int NCB2,int NCB3>
__global__ void __launch_bounds__(384,1) mlp_kernel(
    const float* __restrict__ w1,
    const float* __restrict__ w2, const float* __restrict__ b2,
    const float* __restrict__ w3, const float* __restrict__ b3,
    const float* __restrict__ newxyz, float* __restrict__ out, int off)
{
    constexpr int NT = 384, NW = 12;
    constexpr int R  = BC*K;
    constexpr int LOGK = (K==16) ? 4 : (K==32) ? 5 : 7;
    const float* PQ  = (SCALE==0) ? gPQ0  : (SCALE==1) ? gPQ1  : gPQ2;
    const int*   IDX = (SCALE==0) ? gIdx0 : (SCALE==1) ? gIdx1 : gIdx2;

    extern __shared__ float sm[];
    float* h1  = sm;                    // R  * C1
    float* h2  = h1  + R*C1;            // R  * C2
    float* Rs  = h2  + R*C2;            // BC * C1
    int*   nix = (int*)(Rs + BC*C1);    // R
    int*   mbuf= nix + R;               // BC * C3

    const int tid  = threadIdx.x;
    const int wid  = tid >> 5;
    const int lane = tid & 31;
    const int bs0  = blockIdx.x * BC;
    const int b    = bs0 >> 10;

    for (int e = tid; e < R; e += NT) nix[e] = IDX[(size_t)bs0*K + e];
    for (int e = tid; e < BC*C3; e += NT) mbuf[e] = 0;   // int 0 == float 0.0f (relu floor)
    for (int e = tid; e < BC*C1; e += NT){
        int c = e / C1, ch = e - c*C1;
        const float* wr = w1 + ch*67;
        const float* ce = newxyz + (size_t)(bs0 + c)*3;
        Rs[e] = fmaf(wr[2], ce[2], fmaf(wr[1], ce[1], wr[0]*ce[0]));
    }
    __syncthreads();

    // gather + h1 = relu(PQ[nix] - Rs)
    {
        constexpr int C1v = C1/4;
        const float4* PQ4 = reinterpret_cast<const float4*>(PQ + (size_t)b * NP * C1);
        for (int e = tid; e < R*C1v; e += NT){
            int r = e / C1v, q = e - r*C1v;
            float4 v  = PQ4[(size_t)nix[r]*C1v + q];
            float4 rv = *reinterpret_cast<const float4*>(&Rs[(r/K)*C1 + 4*q]);
            v.x = fmaxf(v.x - rv.x, 0.f); v.y = fmaxf(v.y - rv.y, 0.f);
            v.z = fmaxf(v.z - rv.z, 0.f); v.w = fmaxf(v.w - rv.w, 0.f);
            *reinterpret_cast<float4*>(&h1[r*C1 + 4*q]) = v;
        }
    }
    __syncthreads();

    // ---- layer 2: h2[r, col] = relu(h1[r,:] . w2[col,:] + b2[col]) ----
    {
        constexpr int RB = NW / NCB2;
        const int cb = wid % NCB2, rb = wid / NCB2;
        const int col = cb*32 + lane;
        const int r0 = (R * rb) / RB, r1 = (R * (rb+1)) / RB;
        float4 wr[C1/4];
        load_w<C1>(wr, w2, col);
        const float bb = b2[col];
        int r = r0;
        for (; r + 2 <= r1; r += 2){
            float d0 = dotrow<C1>(&h1[(r  )*C1], wr);
            float d1 = dotrow<C1>(&h1[(r+1)*C1], wr);
            h2[(r  )*C2 + col] = fmaxf(d0 + bb, 0.f);
            h2[(r+1)*C2 + col] = fmaxf(d1 + bb, 0.f);
        }
        if (r < r1)
            h2[r*C2 + col] = fmaxf(dotrow<C1>(&h1[r*C1], wr) + bb, 0.f);
    }
    __syncthreads();

    // ---- layer 3 + fused maxpool over k (per center) ----
    {
        constexpr int RB = NW / NCB3;
        const int cb = wid % NCB3, rb = wid / NCB3;
        const int col = cb*32 + lane;
        const int r0 = (R * rb) / RB, r1 = (R * (rb+1)) / RB;
        float4 wr[C2/4];
        load_w<C2>(wr, w3, col);
        const float bb = b3[col];
        float vm = -1e30f;
        int cen = r0 >> LOGK;
        int r = r0;
        for (; r + 2 <= r1; r += 2){
            float d0 = dotrow<C2>(&h2[(r  )*C2], wr) + bb;
            float d1 = dotrow<C2>(&h2[(r+1)*C2], wr) + bb;
            int c0 = r >> LOGK;
            if (c0 != cen){ atomicMax(&mbuf[cen*C3 + col], __float_as_int(vm)); vm = -1e30f; cen = c0; }
            vm = fmaxf(vm, d0);
            int c1 = (r+1) >> LOGK;
            if (c1 != cen){ atomicMax(&mbuf[cen*C3 + col], __float_as_int(vm)); vm = -1e30f; cen = c1; }
            vm = fmaxf(vm, d1);
        }
        if (r < r1){
            float d0 = dotrow<C2>(&h2[r*C2], wr) + bb;
            int c0 = r >> LOGK;
            if (c0 != cen){ atomicMax(&mbuf[cen*C3 + col], __float_as_int(vm)); vm = -1e30f; cen = c0; }
            vm = fmaxf(vm, d0);
        }
        atomicMax(&mbuf[cen*C3 + col], __float_as_int(vm));
    }
    __syncthreads();

    for (int e = tid; e < BC*C3; e += NT){
        int c = e / C3, col = e - c*C3;
        out[(size_t)(bs0 + c)*320 + off + col] = __int_as_float(mbuf[e]);
    }
}

// smem sizes (bytes)
template<int BC,int K,int C1,int C2,int C3>
constexpr int mlp_smem(){
    return (BC*K*C1 + BC*K*C2 + BC*C1)*4 + (BC*K + BC*C3)*4;
}

// ---------------- launch ----------------
extern "C" void kernel_launch(void* const* d_in, const int* in_sizes, int n_in,
                              void* d_out, int out_size)
{
    const float* xyz  = (const float*)d_in[0];
    const float* feat = (const float*)d_in[1];
    const float* W[3][3]; const float* Bi[3][3];
    for (int i = 0; i < 3; i++)
        for (int j = 0; j < 3; j++){
            W[i][j]  = (const float*)d_in[2 + i*6 + j*2];
            Bi[i][j] = (const float*)d_in[3 + i*6 + j*2];
        }
    float* newxyz   = (float*)d_out;                 // (B, S, 3)
    float* feat_out = (float*)d_out + NB*NS*3;       // (B, S, 320)

    constexpr int SM0 = mlp_smem<16,16,32,32,64>();     // R=256
    constexpr int SM1 = mlp_smem<4,32,64,64,128>();     // R=128
    constexpr int SM2 = mlp_smem<1,128,64,96,128>();    // R=128
    constexpr int SMF = 3*NP*4;

    cudaFuncSetAttribute((const void*)fps_kernel,
                         cudaFuncAttributeMaxDynamicSharedMemorySize, SMF);
    cudaFuncSetAttribute((const void*)mlp_kernel<0,16,16,32,32,64,1,2>,
                         cudaFuncAttributeMaxDynamicSharedMemorySize, SM0);
    cudaFuncSetAttribute((const void*)mlp_kernel<1,4,32,64,64,128,2,4>,
                         cudaFuncAttributeMaxDynamicSharedMemorySize, SM1);
    cudaFuncSetAttribute((const void*)mlp_kernel<2,1,128,64,96,128,3,4>,
                         cudaFuncAttributeMaxDynamicSharedMemorySize, SM2);

    fps_kernel<<<NB, 1024, SMF>>>(xyz, newxyz);
    pq_kernel<<<NB*NP/32, 160>>>(xyz, feat,
        W[0][0], Bi[0][0], W[1][0], Bi[1][0], W[2][0], Bi[2][0]);
    ball_kernel<<<NB*NS, 128>>>(xyz, newxyz);

    mlp_kernel<0,16,16,32,32,64,1,2><<<NB*NS/16, 384, SM0>>>(
        W[0][0], W[0][1], Bi[0][1], W[0][2], Bi[0][2], newxyz, feat_out, 0);
    mlp_kernel<1,4,32,64,64,128,2,4><<<NB*NS/4, 384, SM1>>>(
        W[1][0], W[1][1], Bi[1][1], W[1][2], Bi[1][2], newxyz, feat_out, 64);
    mlp_kernel<2,1,128,64,96,128,3,4><<<NB*NS, 384, SM2>>>(
        W[2][0], W[2][1], Bi[2][1], W[2][2], Bi[2][2], newxyz, feat_out, 192);
}

// round 14
// speedup vs baseline: 1.4004x; 1.4004x over previous
#include <cuda_runtime.h>
#include <cuda_bf16.h>

#define NB 8
#define NP 4096
#define NS 1024

// ---------------- device scratch (static: no allocation allowed) ----------------
__device__ float gPQ0[NB*NP*32];
__device__ float gPQ1[NB*NP*64];
__device__ float gPQ2[NB*NP*64];
__device__ int   gIdx0[NB*NS*16];
__device__ int   gIdx1[NB*NS*32];
__device__ int   gIdx2[NB*NS*128];

// ---------------- mma helpers ----------------
__device__ __forceinline__ void mma_bf16(float* c, const unsigned* a, const unsigned* b){
    asm volatile("mma.sync.aligned.m16n8k16.row.col.f32.bf16.bf16.f32 "
        "{%0,%1,%2,%3}, {%4,%5,%6,%7}, {%8,%9}, {%0,%1,%2,%3};"
        : "+f"(c[0]), "+f"(c[1]), "+f"(c[2]), "+f"(c[3])
        : "r"(a[0]), "r"(a[1]), "r"(a[2]), "r"(a[3]), "r"(b[0]), "r"(b[1]));
}
__device__ __forceinline__ void ldsm4(unsigned* a, unsigned byte_addr){
    asm volatile("ldmatrix.sync.aligned.m8n8.x4.shared.b16 {%0,%1,%2,%3}, [%4];"
        : "=r"(a[0]), "=r"(a[1]), "=r"(a[2]), "=r"(a[3]) : "r"(byte_addr));
}
__device__ __forceinline__ void split_store(__nv_bfloat16* ph, __nv_bfloat16* pl, float v){
    __nv_bfloat16 h = __float2bfloat16(v);
    *ph = h;
    *pl = __float2bfloat16(v - __bfloat162float(h));
}

// ---------------- FPS (unchanged, passing) ----------------
__global__ void __launch_bounds__(1024) fps_kernel(
    const float* __restrict__ xyz, float* __restrict__ newxyz)
{
    extern __shared__ float sfm[];
    __shared__ unsigned long long swarp[32];
    __shared__ float scent[3];
    float* sx = sfm; float* sy = sfm + NP; float* sz = sfm + 2*NP;

    const int b = blockIdx.x, tid = threadIdx.x;
    const float* xb = xyz + (size_t)b * NP * 3;

    float px[4], py[4], pz[4], dist[4];
#pragma unroll
    for (int i = 0; i < 4; i++){
        int p = tid + 1024*i;
        px[i] = xb[3*p]; py[i] = xb[3*p+1]; pz[i] = xb[3*p+2];
        sx[p] = px[i]; sy[p] = py[i]; sz[p] = pz[i];
        dist[i] = 1e10f;
    }
    if (tid == 0){ scent[0] = px[0]; scent[1] = py[0]; scent[2] = pz[0]; }
    __syncthreads();

    for (int it = 0; it < NS; ++it){
        const float cx = scent[0], cy = scent[1], cz = scent[2];
        if (tid == 0){
            float* o = newxyz + ((size_t)b * NS + it) * 3;
            o[0] = cx; o[1] = cy; o[2] = cz;
        }
        float m; unsigned mi;
#pragma unroll
        for (int i = 0; i < 4; i++){
            float dx = px[i]-cx, dy = py[i]-cy, dz = pz[i]-cz;
            float d = __fadd_rn(__fadd_rn(__fmul_rn(dx,dx), __fmul_rn(dy,dy)), __fmul_rn(dz,dz));
            float nd = fminf(dist[i], d);
            dist[i] = nd;
            if (i == 0){ m = nd; mi = (unsigned)tid; }
            else if (nd > m){ m = nd; mi = (unsigned)(tid + 1024*i); }
        }
        unsigned long long best = ((unsigned long long)__float_as_uint(m) << 32)
                                | (unsigned long long)(0xFFFFFFFFu - mi);
#pragma unroll
        for (int off = 16; off; off >>= 1){
            unsigned long long o = __shfl_down_sync(0xFFFFFFFFu, best, off);
            if (o > best) best = o;
        }
        if ((tid & 31) == 0) swarp[tid >> 5] = best;
        __syncthreads();
        if (tid < 32){
            unsigned long long v = swarp[tid];
#pragma unroll
            for (int off = 16; off; off >>= 1){
                unsigned long long o = __shfl_down_sync(0xFFFFFFFFu, v, off);
                if (o > v) v = o;
            }
            if (tid == 0){
                unsigned w = 0xFFFFFFFFu - (unsigned)(v & 0xFFFFFFFFull);
                scent[0] = sx[w]; scent[1] = sy[w]; scent[2] = sz[w];
            }
        }
        __syncthreads();
    }
}

// ---------------- PQ precompute (unchanged, passing) ----------------
__global__ void __launch_bounds__(160) pq_kernel(
    const float* __restrict__ xyz, const float* __restrict__ feat,
    const float* __restrict__ w00, const float* __restrict__ b00,
    const float* __restrict__ w10, const float* __restrict__ b10,
    const float* __restrict__ w20, const float* __restrict__ b20)
{
    __shared__ float sin_[8*68];
    const int tid = threadIdx.x;
    const float* wrow; float bias; float* dst; int C, ch;
    if (tid < 32)      { wrow = w00 + tid*67;      bias = b00[tid];    dst = gPQ0; C = 32; ch = tid; }
    else if (tid < 96) { wrow = w10 + (tid-32)*67; bias = b10[tid-32]; dst = gPQ1; C = 64; ch = tid-32; }
    else               { wrow = w20 + (tid-96)*67; bias = b20[tid-96]; dst = gPQ2; C = 64; ch = tid-96; }
    float wreg[67];
#pragma unroll
    for (int i = 0; i < 67; i++) wreg[i] = wrow[i];

    for (int grp = 0; grp < 4; grp++){
        int gbase = blockIdx.x * 32 + grp * 8;
        __syncthreads();
        for (int t = tid; t < 8*67; t += 160){
            int pt = t / 67, c = t - 67*pt;
            int g = gbase + pt;
            sin_[pt*68 + c] = (c < 3) ? xyz[(size_t)g*3 + c] : feat[(size_t)g*64 + (c-3)];
        }
        __syncthreads();
#pragma unroll 1
        for (int pt = 0; pt < 8; pt++){
            const float* inp = &sin_[pt*68];
            float a0 = bias, a1 = 0.f;
#pragma unroll
            for (int i = 0; i < 8; i++){
                float4 v0 = *reinterpret_cast<const float4*>(inp + 8*i);
                float4 v1 = *reinterpret_cast<const float4*>(inp + 8*i + 4);
                a0 = fmaf(v0.x, wreg[8*i+0], a0); a0 = fmaf(v0.y, wreg[8*i+1], a0);
                a0 = fmaf(v0.z, wreg[8*i+2], a0); a0 = fmaf(v0.w, wreg[8*i+3], a0);
                a1 = fmaf(v1.x, wreg[8*i+4], a1); a1 = fmaf(v1.y, wreg[8*i+5], a1);
                a1 = fmaf(v1.z, wreg[8*i+6], a1); a1 = fmaf(v1.w, wreg[8*i+7], a1);
            }
            a0 = fmaf(inp[64], wreg[64], a0);
            a1 = fmaf(inp[65], wreg[65], a1);
            a0 = fmaf(inp[66], wreg[66], a0);
            dst[(size_t)(gbase + pt) * C + ch] = a0 + a1;
        }
    }
}

// ---------------- ball query (unchanged, passing) ----------------
__global__ void __launch_bounds__(128) ball_kernel(
    const float* __restrict__ xyz, const float* __restrict__ newxyz)
{
    const int bs = blockIdx.x;
    const int b = bs >> 10;
    const int tid = threadIdx.x;
    const int w = tid >> 5, lane = tid & 31;
    const float cx = newxyz[(size_t)bs*3+0];
    const float cy = newxyz[(size_t)bs*3+1];
    const float cz = newxyz[(size_t)bs*3+2];
    const float nn = __fadd_rn(__fadd_rn(__fmul_rn(cx,cx), __fmul_rn(cy,cy)), __fmul_rn(cz,cz));
    __shared__ int cnt[3], wcnt[3][4], sfirst[3];
    if (tid < 3){ cnt[tid] = 0; sfirst[tid] = 0; }
    __syncthreads();
    const float* xb = xyz + (size_t)b * NP * 3;

    for (int jb = 0; jb < NP; jb += 128){
        int j = jb + tid;
        float x = xb[3*j], y = xb[3*j+1], z = xb[3*j+2];
        float pp  = __fadd_rn(__fadd_rn(__fmul_rn(x,x), __fmul_rn(y,y)), __fmul_rn(z,z));
        float dot = __fadd_rn(__fadd_rn(__fmul_rn(cx,x), __fmul_rn(cy,y)), __fmul_rn(cz,z));
        float sqd = __fsub_rn(__fadd_rn(nn, pp), __fmul_rn(2.0f, dot));
        bool in0 = !(sqd > 0.01f);
        bool in1 = !(sqd > 0.04f);
        bool in2 = !(sqd > 0.16f);
        unsigned m0 = __ballot_sync(0xFFFFFFFFu, in0);
        unsigned m1 = __ballot_sync(0xFFFFFFFFu, in1);
        unsigned m2 = __ballot_sync(0xFFFFFFFFu, in2);
        if (lane == 0){ wcnt[0][w]=__popc(m0); wcnt[1][w]=__popc(m1); wcnt[2][w]=__popc(m2); }
        __syncthreads();
        unsigned lm = (1u << lane) - 1u;
        int b0 = cnt[0], b1 = cnt[1], b2 = cnt[2];
        for (int ww = 0; ww < w; ww++){ b0 += wcnt[0][ww]; b1 += wcnt[1][ww]; b2 += wcnt[2][ww]; }
        if (in0){ int p = b0 + __popc(m0 & lm); if (p == 0) sfirst[0] = j; if (p < 16)  gIdx0[(size_t)bs*16  + p] = j; }
        if (in1){ int p = b1 + __popc(m1 & lm); if (p == 0) sfirst[1] = j; if (p < 32)  gIdx1[(size_t)bs*32  + p] = j; }
        if (in2){ int p = b2 + __popc(m2 & lm); if (p == 0) sfirst[2] = j; if (p < 128) gIdx2[(size_t)bs*128 + p] = j; }
        __syncthreads();
        if (tid == 0){
            cnt[0] += wcnt[0][0]+wcnt[0][1]+wcnt[0][2]+wcnt[0][3];
            cnt[1] += wcnt[1][0]+wcnt[1][1]+wcnt[1][2]+wcnt[1][3];
            cnt[2] += wcnt[2][0]+wcnt[2][1]+wcnt[2][2]+wcnt[2][3];
        }
        __syncthreads();
        if (cnt[0] >= 16 && cnt[1] >= 32 && cnt[2] >= 128) break;
    }
    int f0 = sfirst[0], f1 = sfirst[1], f2 = sfirst[2];
    for (int q = cnt[0] + tid; q < 16;  q += 128) gIdx0[(size_t)bs*16  + q] = f0;
    for (int q = cnt[1] + tid; q < 32;  q += 128) gIdx1[(size_t)bs*32  + q] = f1;
    for (int q = cnt[2] + tid; q < 128; q += 128) gIdx2[(size_t)bs*128 + q] = f2;
}

// ---------------- MLP via bf16-split warp MMA ----------------
// R = BC*K = 128 rows per CTA, 8 M-tiles of 16 rows (tile == center-aligned).
// Per M-tile: gather+split h1 -> L2 mma (3-term split) -> relu+split h2 -> L3 mma -> rowmax -> smem atomicMax.
template<int SCALE,int BC,int K,int C1,int C2,int C3>
__global__ void __launch_bounds__(128,1) mlp_kernel(
    const float* __restrict__ w1,
    const float* __restrict__ w2, const float* __restrict__ b2,
    const float* __restrict__ w3, const float* __restrict__ b3,
    const float* __restrict__ newxyz, float* __restrict__ out, int off)
{
    constexpr int R = 128, MT = 8;
    constexpr int P1 = C1 + 8, P2 = C2 + 8;          // row strides (bf16 elems), mult of 8 => 16B-aligned rows
    constexpr int NT2 = C2/8, NT3 = C3/8;
    constexpr int KT2 = C1/16, KT3 = C2/16;
    static_assert(R == BC*K, "rows");

    const float* PQ  = (SCALE==0) ? gPQ0  : (SCALE==1) ? gPQ1  : gPQ2;
    const int*   IDX = (SCALE==0) ? gIdx0 : (SCALE==1) ? gIdx1 : gIdx2;

    extern __shared__ char smraw[];
    __nv_bfloat16* w2h = reinterpret_cast<__nv_bfloat16*>(smraw);
    __nv_bfloat16* w2l = w2h + C2*P1;
    __nv_bfloat16* w3h = w2l + C2*P1;
    __nv_bfloat16* w3l = w3h + C3*P2;
    __nv_bfloat16* h1h = w3l + C3*P2;
    __nv_bfloat16* h1l = h1h + 16*P1;
    __nv_bfloat16* h2h = h1l + 16*P1;
    __nv_bfloat16* h2l = h2h + 16*P2;
    float* b2s = reinterpret_cast<float*>(h2l + 16*P2);
    float* b3s = b2s + C2;
    float* Rs  = b3s + C3;                            // BC*C1
    int*   nix = reinterpret_cast<int*>(Rs + BC*C1);  // R
    int*   mbuf= nix + R;                             // BC*C3

    const int tid = threadIdx.x, lane = tid & 31, wid = tid >> 5;
    const int gid = lane >> 2, tig = lane & 3;
    const int bs0 = blockIdx.x * BC, b = bs0 >> 10;

    // stage split weights + biases + indices
    for (int e = tid; e < C2*C1; e += 128){
        int r = e / C1, c = e - r*C1;
        split_store(&w2h[r*P1 + c], &w2l[r*P1 + c], w2[e]);
    }
    for (int e = tid; e < C3*C2; e += 128){
        int r = e / C2, c = e - r*C2;
        split_store(&w3h[r*P2 + c], &w3l[r*P2 + c], w3[e]);
    }
    for (int e = tid; e < C2; e += 128) b2s[e] = b2[e];
    for (int e = tid; e < C3; e += 128) b3s[e] = b3[e];
    for (int e = tid; e < R; e += 128) nix[e] = IDX[(size_t)bs0*K + e];
    for (int e = tid; e < BC*C3; e += 128) mbuf[e] = 0;   // relu floor
    for (int e = tid; e < BC*C1; e += 128){
        int c = e / C1, ch = e - c*C1;
        const float* wr = w1 + ch*67;
        const float* ce = newxyz + (size_t)(bs0 + c)*3;
        Rs[e] = fmaf(wr[2], ce[2], fmaf(wr[1], ce[1], wr[0]*ce[0]));
    }
    __syncthreads();

    const unsigned h1h_s = (unsigned)__cvta_generic_to_shared(h1h);
    const unsigned h1l_s = (unsigned)__cvta_generic_to_shared(h1l);
    const unsigned h2h_s = (unsigned)__cvta_generic_to_shared(h2h);
    const unsigned h2l_s = (unsigned)__cvta_generic_to_shared(h2l);
    // ldmatrix lane offsets (bytes): lanes 0-15 -> rows 0-15 col 0; lanes 16-31 -> rows 0-15 col 8
    const unsigned lmoff1 = 2u * ((unsigned)(lane & 15) * P1 + (unsigned)(lane >> 4) * 8);
    const unsigned lmoff2 = 2u * ((unsigned)(lane & 15) * P2 + (unsigned)(lane >> 4) * 8);

    const float4* PQ4 = reinterpret_cast<const float4*>(PQ + (size_t)b * NP * C1);

#pragma unroll 1
    for (int mt = 0; mt < MT; mt++){
        // ---- gather 16 rows, split to bf16 planes ----
        constexpr int C1v = C1/4;
        for (int e = tid; e < 16*C1v; e += 128){
            int lr = e / C1v, q = e - lr*C1v;
            int r = mt*16 + lr;
            float4 v = PQ4[(size_t)nix[r]*C1v + q];
            const float* rs = &Rs[(r/K)*C1 + 4*q];
            int base = lr*P1 + 4*q;
            split_store(&h1h[base+0], &h1l[base+0], fmaxf(v.x - rs[0], 0.f));
            split_store(&h1h[base+1], &h1l[base+1], fmaxf(v.y - rs[1], 0.f));
            split_store(&h1h[base+2], &h1l[base+2], fmaxf(v.z - rs[2], 0.f));
            split_store(&h1h[base+3], &h1l[base+3], fmaxf(v.w - rs[3], 0.f));
        }
        __syncthreads();

        // ---- layer 2 ----
#pragma unroll 1
        for (int nt = wid; nt < NT2; nt += 4){
            int n0 = nt*8;
            float bb0 = b2s[n0 + 2*tig], bb1 = b2s[n0 + 2*tig + 1];
            float chh[4] = {bb0, bb1, bb0, bb1};
            float cx_[4] = {0.f, 0.f, 0.f, 0.f};
#pragma unroll
            for (int kt = 0; kt < KT2; kt++){
                unsigned ah[4], al[4], bh[2], bl[2];
                ldsm4(ah, h1h_s + lmoff1 + 2u*(unsigned)(kt*16));
                ldsm4(al, h1l_s + lmoff1 + 2u*(unsigned)(kt*16));
                int wrow = (n0 + gid)*P1 + kt*16 + 2*tig;
                bh[0] = *reinterpret_cast<const unsigned*>(&w2h[wrow]);
                bh[1] = *reinterpret_cast<const unsigned*>(&w2h[wrow + 8]);
                bl[0] = *reinterpret_cast<const unsigned*>(&w2l[wrow]);
                bl[1] = *reinterpret_cast<const unsigned*>(&w2l[wrow + 8]);
                mma_bf16(chh, ah, bh);
                mma_bf16(cx_, al, bh);
                mma_bf16(cx_, ah, bl);
            }
            int c0 = n0 + 2*tig;
            float v0 = fmaxf(chh[0] + cx_[0], 0.f);
            float v1 = fmaxf(chh[1] + cx_[1], 0.f);
            float v2 = fmaxf(chh[2] + cx_[2], 0.f);
            float v3 = fmaxf(chh[3] + cx_[3], 0.f);
            split_store(&h2h[gid*P2 + c0],       &h2l[gid*P2 + c0],       v0);
            split_store(&h2h[gid*P2 + c0 + 1],   &h2l[gid*P2 + c0 + 1],   v1);
            split_store(&h2h[(gid+8)*P2 + c0],   &h2l[(gid+8)*P2 + c0],   v2);
            split_store(&h2h[(gid+8)*P2 + c0+1], &h2l[(gid+8)*P2 + c0+1], v3);
        }
        __syncthreads();

        // ---- layer 3 + maxpool ----
        const int cen = (mt*16) / K;
#pragma unroll 1
        for (int nt = wid; nt < NT3; nt += 4){
            int n0 = nt*8;
            float chh[4] = {0.f, 0.f, 0.f, 0.f};
            float cx_[4] = {0.f, 0.f, 0.f, 0.f};
#pragma unroll
            for (int kt = 0; kt < KT3; kt++){
                unsigned ah[4], al[4], bh[2], bl[2];
                ldsm4(ah, h2h_s + lmoff2 + 2u*(unsigned)(kt*16));
                ldsm4(al, h2l_s + lmoff2 + 2u*(unsigned)(kt*16));
                int wrow = (n0 + gid)*P2 + kt*16 + 2*tig;
                bh[0] = *reinterpret_cast<const unsigned*>(&w3h[wrow]);
                bh[1] = *reinterpret_cast<const unsigned*>(&w3h[wrow + 8]);
                bl[0] = *reinterpret_cast<const unsigned*>(&w3l[wrow]);
                bl[1] = *reinterpret_cast<const unsigned*>(&w3l[wrow + 8]);
                mma_bf16(chh, ah, bh);
                mma_bf16(cx_, al, bh);
                mma_bf16(cx_, ah, bl);
            }
            float v0 = fmaxf(chh[0] + cx_[0], chh[2] + cx_[2]);   // rows g, g+8
            float v1 = fmaxf(chh[1] + cx_[1], chh[3] + cx_[3]);
            v0 = fmaxf(v0, __shfl_xor_sync(0xFFFFFFFFu, v0, 4));
            v0 = fmaxf(v0, __shfl_xor_sync(0xFFFFFFFFu, v0, 8));
            v0 = fmaxf(v0, __shfl_xor_sync(0xFFFFFFFFu, v0, 16));
            v1 = fmaxf(v1, __shfl_xor_sync(0xFFFFFFFFu, v1, 4));
            v1 = fmaxf(v1, __shfl_xor_sync(0xFFFFFFFFu, v1, 8));
            v1 = fmaxf(v1, __shfl_xor_sync(0xFFFFFFFFu, v1, 16));
            if (gid == 0){
                int c0 = n0 + 2*tig;
                atomicMax(&mbuf[cen*C3 + c0],     __float_as_int(v0 + b3s[c0]));
                atomicMax(&mbuf[cen*C3 + c0 + 1], __float_as_int(v1 + b3s[c0 + 1]));
            }
        }
        __syncthreads();
    }

    for (int e = tid; e < BC*C3; e += 128){
        int c = e / C3, col = e - c*C3;
        out[(size_t)(bs0 + c)*320 + off + col] = __int_as_float(mbuf[e]);
    }
}

// smem bytes
template<int BC,int K,int C1,int C2,int C3>
constexpr int mma_smem(){
    constexpr int P1 = C1 + 8, P2 = C2 + 8;
    return 2*(2*C2*P1 + 2*C3*P2 + 2*16*P1 + 2*16*P2)
         + 4*(C2 + C3 + BC*C1) + 4*(128 + BC*C3);
}

// ---------------- launch ----------------
extern "C" void kernel_launch(void* const* d_in, const int* in_sizes, int n_in,
                              void* d_out, int out_size)
{
    const float* xyz  = (const float*)d_in[0];
    const float* feat = (const float*)d_in[1];
    const float* W[3][3]; const float* Bi[3][3];
    for (int i = 0; i < 3; i++)
        for (int j = 0; j < 3; j++){
            W[i][j]  = (const float*)d_in[2 + i*6 + j*2];
            Bi[i][j] = (const float*)d_in[3 + i*6 + j*2];
        }
    float* newxyz   = (float*)d_out;                 // (B, S, 3)
    float* feat_out = (float*)d_out + NB*NS*3;       // (B, S, 320)

    constexpr int SM0 = mma_smem<8,16,32,32,64>();    // ~24KB
    constexpr int SM1 = mma_smem<4,32,64,64,128>();   // ~69KB
    constexpr int SM2 = mma_smem<1,128,64,96,128>();  // ~94KB
    constexpr int SMF = 3*NP*4;

    cudaFuncSetAttribute((const void*)fps_kernel,
                         cudaFuncAttributeMaxDynamicSharedMemorySize, SMF);
    cudaFuncSetAttribute((const void*)mlp_kernel<0,8,16,32,32,64>,
                         cudaFuncAttributeMaxDynamicSharedMemorySize, SM0);
    cudaFuncSetAttribute((const void*)mlp_kernel<1,4,32,64,64,128>,
                         cudaFuncAttributeMaxDynamicSharedMemorySize, SM1);
    cudaFuncSetAttribute((const void*)mlp_kernel<2,1,128,64,96,128>,
                         cudaFuncAttributeMaxDynamicSharedMemorySize, SM2);

    fps_kernel<<<NB, 1024, SMF>>>(xyz, newxyz);
    pq_kernel<<<NB*NP/32, 160>>>(xyz, feat,
        W[0][0], Bi[0][0], W[1][0], Bi[1][0], W[2][0], Bi[2][0]);
    ball_kernel<<<NB*NS, 128>>>(xyz, newxyz);

    mlp_kernel<0,8,16,32,32,64><<<NB*NS/8, 128, SM0>>>(
        W[0][0], W[0][1], Bi[0][1], W[0][2], Bi[0][2], newxyz, feat_out, 0);
    mlp_kernel<1,4,32,64,64,128><<<NB*NS/4, 128, SM1>>>(
        W[1][0], W[1][1], Bi[1][1], W[1][2], Bi[1][2], newxyz, feat_out, 64);
    mlp_kernel<2,1,128,64,96,128><<<NB*NS, 128, SM2>>>(
        W[2][0], W[2][1], Bi[2][1], W[2][2], Bi[2][2], newxyz, feat_out, 192);
}

// round 17
// speedup vs baseline: 1.7513x; 1.2506x over previous
#include <cuda_runtime.h>
#include <cuda_bf16.h>

#define NB 8
#define NP 4096
#define NS 1024

// ---------------- device scratch (static: no allocation allowed) ----------------
__device__ float gPQ0[NB*NP*32];
__device__ float gPQ1[NB*NP*64];
__device__ float gPQ2[NB*NP*64];
__device__ int   gIdx0[NB*NS*16];
__device__ int   gIdx1[NB*NS*32];
__device__ int   gIdx2[NB*NS*128];

// pre-split bf16 weight planes, padded to P = C+8 row stride
__device__ __align__(16) __nv_bfloat16 gW2H0[32*40],  gW2L0[32*40],  gW3H0[64*40],   gW3L0[64*40];
__device__ __align__(16) __nv_bfloat16 gW2H1[64*72],  gW2L1[64*72],  gW3H1[128*72],  gW3L1[128*72];
__device__ __align__(16) __nv_bfloat16 gW2H2[96*72],  gW2L2[96*72],  gW3H2[128*104], gW3L2[128*104];

// ---------------- mma helpers ----------------
__device__ __forceinline__ void mma_bf16(float* c, const unsigned* a, const unsigned* b){
    asm volatile("mma.sync.aligned.m16n8k16.row.col.f32.bf16.bf16.f32 "
        "{%0,%1,%2,%3}, {%4,%5,%6,%7}, {%8,%9}, {%0,%1,%2,%3};"
        : "+f"(c[0]), "+f"(c[1]), "+f"(c[2]), "+f"(c[3])
        : "r"(a[0]), "r"(a[1]), "r"(a[2]), "r"(a[3]), "r"(b[0]), "r"(b[1]));
}
__device__ __forceinline__ void ldsm4(unsigned* a, unsigned byte_addr){
    asm volatile("ldmatrix.sync.aligned.m8n8.x4.shared.b16 {%0,%1,%2,%3}, [%4];"
        : "=r"(a[0]), "=r"(a[1]), "=r"(a[2]), "=r"(a[3]) : "r"(byte_addr));
}
__device__ __forceinline__ void split_store(__nv_bfloat16* ph, __nv_bfloat16* pl, float v){
    __nv_bfloat16 h = __float2bfloat16(v);
    *ph = h;
    *pl = __float2bfloat16(v - __bfloat162float(h));
}
// split a pair (a,b) into packed bf16x2 hi/lo words
__device__ __forceinline__ void split2(unsigned& hi, unsigned& lo, float a, float b){
    __nv_bfloat16 ha = __float2bfloat16(a), hb = __float2bfloat16(b);
    __nv_bfloat162 h; h.x = ha; h.y = hb;
    __nv_bfloat162 l;
    l.x = __float2bfloat16(a - __bfloat162float(ha));
    l.y = __float2bfloat16(b - __bfloat162float(hb));
    hi = *reinterpret_cast<unsigned*>(&h);
    lo = *reinterpret_cast<unsigned*>(&l);
}

// ---------------- weight pre-split (runs once per call, tiny) ----------------
__global__ void wsplit_kernel(
    const float* __restrict__ w20, const float* __restrict__ w30,
    const float* __restrict__ w21, const float* __restrict__ w31,
    const float* __restrict__ w22, const float* __restrict__ w32)
{
    const int tid = blockIdx.x*blockDim.x + threadIdx.x;
    const int nth = gridDim.x*blockDim.x;
    for (int e = tid; e < 32*32;  e += nth){ int r=e/32, c=e-32*r;  split_store(&gW2H0[r*40+c],  &gW2L0[r*40+c],  w20[e]); }
    for (int e = tid; e < 64*32;  e += nth){ int r=e/32, c=e-32*r;  split_store(&gW3H0[r*40+c],  &gW3L0[r*40+c],  w30[e]); }
    for (int e = tid; e < 64*64;  e += nth){ int r=e/64, c=e-64*r;  split_store(&gW2H1[r*72+c],  &gW2L1[r*72+c],  w21[e]); }
    for (int e = tid; e < 128*64; e += nth){ int r=e/64, c=e-64*r;  split_store(&gW3H1[r*72+c],  &gW3L1[r*72+c],  w31[e]); }
    for (int e = tid; e < 96*64;  e += nth){ int r=e/64, c=e-64*r;  split_store(&gW2H2[r*72+c],  &gW2L2[r*72+c],  w22[e]); }
    for (int e = tid; e < 128*96; e += nth){ int r=e/96, c=e-96*r;  split_store(&gW3H2[r*104+c], &gW3L2[r*104+c], w32[e]); }
}

// ---------------- FPS (unchanged, passing) ----------------
__global__ void __launch_bounds__(1024) fps_kernel(
    const float* __restrict__ xyz, float* __restrict__ newxyz)
{
    extern __shared__ float sfm[];
    __shared__ unsigned long long swarp[32];
    __shared__ float scent[3];
    float* sx = sfm; float* sy = sfm + NP; float* sz = sfm + 2*NP;

    const int b = blockIdx.x, tid = threadIdx.x;
    const float* xb = xyz + (size_t)b * NP * 3;

    float px[4], py[4], pz[4], dist[4];
#pragma unroll
    for (int i = 0; i < 4; i++){
        int p = tid + 1024*i;
        px[i] = xb[3*p]; py[i] = xb[3*p+1]; pz[i] = xb[3*p+2];
        sx[p] = px[i]; sy[p] = py[i]; sz[p] = pz[i];
        dist[i] = 1e10f;
    }
    if (tid == 0){ scent[0] = px[0]; scent[1] = py[0]; scent[2] = pz[0]; }
    __syncthreads();

    for (int it = 0; it < NS; ++it){
        const float cx = scent[0], cy = scent[1], cz = scent[2];
        if (tid == 0){
            float* o = newxyz + ((size_t)b * NS + it) * 3;
            o[0] = cx; o[1] = cy; o[2] = cz;
        }
        float m; unsigned mi;
#pragma unroll
        for (int i = 0; i < 4; i++){
            float dx = px[i]-cx, dy = py[i]-cy, dz = pz[i]-cz;
            float d = __fadd_rn(__fadd_rn(__fmul_rn(dx,dx), __fmul_rn(dy,dy)), __fmul_rn(dz,dz));
            float nd = fminf(dist[i], d);
            dist[i] = nd;
            if (i == 0){ m = nd; mi = (unsigned)tid; }
            else if (nd > m){ m = nd; mi = (unsigned)(tid + 1024*i); }
        }
        unsigned long long best = ((unsigned long long)__float_as_uint(m) << 32)
                                | (unsigned long long)(0xFFFFFFFFu - mi);
#pragma unroll
        for (int off = 16; off; off >>= 1){
            unsigned long long o = __shfl_down_sync(0xFFFFFFFFu, best, off);
            if (o > best) best = o;
        }
        if ((tid & 31) == 0) swarp[tid >> 5] = best;
        __syncthreads();
        if (tid < 32){
            unsigned long long v = swarp[tid];
#pragma unroll
            for (int off = 16; off; off >>= 1){
                unsigned long long o = __shfl_down_sync(0xFFFFFFFFu, v, off);
                if (o > v) v = o;
            }
            if (tid == 0){
                unsigned w = 0xFFFFFFFFu - (unsigned)(v & 0xFFFFFFFFull);
                scent[0] = sx[w]; scent[1] = sy[w]; scent[2] = sz[w];
            }
        }
        __syncthreads();
    }
}

// ---------------- PQ precompute (unchanged, passing) ----------------
__global__ void __launch_bounds__(160) pq_kernel(
    const float* __restrict__ xyz, const float* __restrict__ feat,
    const float* __restrict__ w00, const float* __restrict__ b00,
    const float* __restrict__ w10, const float* __restrict__ b10,
    const float* __restrict__ w20, const float* __restrict__ b20)
{
    __shared__ float sin_[8*68];
    const int tid = threadIdx.x;
    const float* wrow; float bias; float* dst; int C, ch;
    if (tid < 32)      { wrow = w00 + tid*67;      bias = b00[tid];    dst = gPQ0; C = 32; ch = tid; }
    else if (tid < 96) { wrow = w10 + (tid-32)*67; bias = b10[tid-32]; dst = gPQ1; C = 64; ch = tid-32; }
    else               { wrow = w20 + (tid-96)*67; bias = b20[tid-96]; dst = gPQ2; C = 64; ch = tid-96; }
    float wreg[67];
#pragma unroll
    for (int i = 0; i < 67; i++) wreg[i] = wrow[i];

    for (int grp = 0; grp < 4; grp++){
        int gbase = blockIdx.x * 32 + grp * 8;
        __syncthreads();
        for (int t = tid; t < 8*67; t += 160){
            int pt = t / 67, c = t - 67*pt;
            int g = gbase + pt;
            sin_[pt*68 + c] = (c < 3) ? xyz[(size_t)g*3 + c] : feat[(size_t)g*64 + (c-3)];
        }
        __syncthreads();
#pragma unroll 1
        for (int pt = 0; pt < 8; pt++){
            const float* inp = &sin_[pt*68];
            float a0 = bias, a1 = 0.f;
#pragma unroll
            for (int i = 0; i < 8; i++){
                float4 v0 = *reinterpret_cast<const float4*>(inp + 8*i);
                float4 v1 = *reinterpret_cast<const float4*>(inp + 8*i + 4);
                a0 = fmaf(v0.x, wreg[8*i+0], a0); a0 = fmaf(v0.y, wreg[8*i+1], a0);
                a0 = fmaf(v0.z, wreg[8*i+2], a0); a0 = fmaf(v0.w, wreg[8*i+3], a0);
                a1 = fmaf(v1.x, wreg[8*i+4], a1); a1 = fmaf(v1.y, wreg[8*i+5], a1);
                a1 = fmaf(v1.z, wreg[8*i+6], a1); a1 = fmaf(v1.w, wreg[8*i+7], a1);
            }
            a0 = fmaf(inp[64], wreg[64], a0);
            a1 = fmaf(inp[65], wreg[65], a1);
            a0 = fmaf(inp[66], wreg[66], a0);
            dst[(size_t)(gbase + pt) * C + ch] = a0 + a1;
        }
    }
}

// ---------------- ball query (unchanged, passing) ----------------
__global__ void __launch_bounds__(128) ball_kernel(
    const float* __restrict__ xyz, const float* __restrict__ newxyz)
{
    const int bs = blockIdx.x;
    const int b = bs >> 10;
    const int tid = threadIdx.x;
    const int w = tid >> 5, lane = tid & 31;
    const float cx = newxyz[(size_t)bs*3+0];
    const float cy = newxyz[(size_t)bs*3+1];
    const float cz = newxyz[(size_t)bs*3+2];
    const float nn = __fadd_rn(__fadd_rn(__fmul_rn(cx,cx), __fmul_rn(cy,cy)), __fmul_rn(cz,cz));
    __shared__ int cnt[3], wcnt[3][4], sfirst[3];
    if (tid < 3){ cnt[tid] = 0; sfirst[tid] = 0; }
    __syncthreads();
    const float* xb = xyz + (size_t)b * NP * 3;

    for (int jb = 0; jb < NP; jb += 128){
        int j = jb + tid;
        float x = xb[3*j], y = xb[3*j+1], z = xb[3*j+2];
        float pp  = __fadd_rn(__fadd_rn(__fmul_rn(x,x), __fmul_rn(y,y)), __fmul_rn(z,z));
        float dot = __fadd_rn(__fadd_rn(__fmul_rn(cx,x), __fmul_rn(cy,y)), __fmul_rn(cz,z));
        float sqd = __fsub_rn(__fadd_rn(nn, pp), __fmul_rn(2.0f, dot));
        bool in0 = !(sqd > 0.01f);
        bool in1 = !(sqd > 0.04f);
        bool in2 = !(sqd > 0.16f);
        unsigned m0 = __ballot_sync(0xFFFFFFFFu, in0);
        unsigned m1 = __ballot_sync(0xFFFFFFFFu, in1);
        unsigned m2 = __ballot_sync(0xFFFFFFFFu, in2);
        if (lane == 0){ wcnt[0][w]=__popc(m0); wcnt[1][w]=__popc(m1); wcnt[2][w]=__popc(m2); }
        __syncthreads();
        unsigned lm = (1u << lane) - 1u;
        int b0 = cnt[0], b1 = cnt[1], b2 = cnt[2];
        for (int ww = 0; ww < w; ww++){ b0 += wcnt[0][ww]; b1 += wcnt[1][ww]; b2 += wcnt[2][ww]; }
        if (in0){ int p = b0 + __popc(m0 & lm); if (p == 0) sfirst[0] = j; if (p < 16)  gIdx0[(size_t)bs*16  + p] = j; }
        if (in1){ int p = b1 + __popc(m1 & lm); if (p == 0) sfirst[1] = j; if (p < 32)  gIdx1[(size_t)bs*32  + p] = j; }
        if (in2){ int p = b2 + __popc(m2 & lm); if (p == 0) sfirst[2] = j; if (p < 128) gIdx2[(size_t)bs*128 + p] = j; }
        __syncthreads();
        if (tid == 0){
            cnt[0] += wcnt[0][0]+wcnt[0][1]+wcnt[0][2]+wcnt[0][3];
            cnt[1] += wcnt[1][0]+wcnt[1][1]+wcnt[1][2]+wcnt[1][3];
            cnt[2] += wcnt[2][0]+wcnt[2][1]+wcnt[2][2]+wcnt[2][3];
        }
        __syncthreads();
        if (cnt[0] >= 16 && cnt[1] >= 32 && cnt[2] >= 128) break;
    }
    int f0 = sfirst[0], f1 = sfirst[1], f2 = sfirst[2];
    for (int q = cnt[0] + tid; q < 16;  q += 128) gIdx0[(size_t)bs*16  + q] = f0;
    for (int q = cnt[1] + tid; q < 32;  q += 128) gIdx1[(size_t)bs*32  + q] = f1;
    for (int q = cnt[2] + tid; q < 128; q += 128) gIdx2[(size_t)bs*128 + q] = f2;
}

// ---------------- MLP via bf16-split warp MMA, 8 warps, 32-row groups ----------------
template<int SCALE,int BC,int K,int C1,int C2,int C3>
__global__ void __launch_bounds__(256,1) mlp_kernel(
    const float* __restrict__ w1,
    const float* __restrict__ b2, const float* __restrict__ b3,
    const float* __restrict__ newxyz, float* __restrict__ out, int off)
{
    constexpr int NT = 256;
    constexpr int R  = BC*K;
    constexpr int NG = R/32;
    constexpr int P1 = C1 + 8, P2 = C2 + 8;
    constexpr int NT2 = C2/8, NT3 = C3/8;
    constexpr int KT2 = C1/16, KT3 = C2/16;

    const float* PQ  = (SCALE==0) ? gPQ0  : (SCALE==1) ? gPQ1  : gPQ2;
    const int*   IDX = (SCALE==0) ? gIdx0 : (SCALE==1) ? gIdx1 : gIdx2;
    const __nv_bfloat16* w2h_g = (SCALE==0) ? gW2H0 : (SCALE==1) ? gW2H1 : gW2H2;
    const __nv_bfloat16* w2l_g = (SCALE==0) ? gW2L0 : (SCALE==1) ? gW2L1 : gW2L2;
    const __nv_bfloat16* w3h_g = (SCALE==0) ? gW3H0 : (SCALE==1) ? gW3H1 : gW3H2;
    const __nv_bfloat16* w3l_g = (SCALE==0) ? gW3L0 : (SCALE==1) ? gW3L1 : gW3L2;

    extern __shared__ char smraw[];
    __nv_bfloat16* w2h = reinterpret_cast<__nv_bfloat16*>(smraw);
    __nv_bfloat16* w2l = w2h + C2*P1;
    __nv_bfloat16* w3h = w2l + C2*P1;
    __nv_bfloat16* w3l = w3h + C3*P2;
    __nv_bfloat16* h1h = w3l + C3*P2;
    __nv_bfloat16* h1l = h1h + 32*P1;
    __nv_bfloat16* h2h = h1l + 32*P1;
    __nv_bfloat16* h2l = h2h + 32*P2;
    float* b2s = reinterpret_cast<float*>(h2l + 32*P2);
    float* b3s = b2s + C2;
    float* Rs  = b3s + C3;                            // BC*C1
    int*   nix = reinterpret_cast<int*>(Rs + BC*C1);  // R
    int*   mbuf= nix + R;                             // BC*C3

    const int tid = threadIdx.x, lane = tid & 31, wid = tid >> 5;
    const int gid = lane >> 2, tig = lane & 3;
    const int bs0 = blockIdx.x * BC, b = bs0 >> 10;

    // stage pre-split weights via int4 copies
    {
        auto cp = [&](__nv_bfloat16* d, const __nv_bfloat16* s, int n16){
            const int4* sp = reinterpret_cast<const int4*>(s);
            int4* dp = reinterpret_cast<int4*>(d);
            for (int e = tid; e < n16; e += NT) dp[e] = sp[e];
        };
        cp(w2h, w2h_g, C2*P1/8); cp(w2l, w2l_g, C2*P1/8);
        cp(w3h, w3h_g, C3*P2/8); cp(w3l, w3l_g, C3*P2/8);
    }
    for (int e = tid; e < C2; e += NT) b2s[e] = b2[e];
    for (int e = tid; e < C3; e += NT) b3s[e] = b3[e];
    for (int e = tid; e < R; e += NT) nix[e] = IDX[(size_t)bs0*K + e];
    for (int e = tid; e < BC*C3; e += NT) mbuf[e] = 0;   // relu floor
    for (int e = tid; e < BC*C1; e += NT){
        int c = e / C1, ch = e - c*C1;
        const float* wr = w1 + ch*67;
        const float* ce = newxyz + (size_t)(bs0 + c)*3;
        Rs[e] = fmaf(wr[2], ce[2], fmaf(wr[1], ce[1], wr[0]*ce[0]));
    }
    __syncthreads();

    const unsigned h1h_s = (unsigned)__cvta_generic_to_shared(h1h);
    const unsigned h1l_s = (unsigned)__cvta_generic_to_shared(h1l);
    const unsigned h2h_s = (unsigned)__cvta_generic_to_shared(h2h);
    const unsigned h2l_s = (unsigned)__cvta_generic_to_shared(h2l);
    const unsigned lmb1 = 2u * ((unsigned)(lane & 15) * P1 + (unsigned)(lane >> 4) * 8);
    const unsigned lmb2 = 2u * ((unsigned)(lane & 15) * P2 + (unsigned)(lane >> 4) * 8);

    const float4* PQ4 = reinterpret_cast<const float4*>(PQ + (size_t)b * NP * C1);
    constexpr int C1v = C1/4;

#pragma unroll 1
    for (int grp = 0; grp < NG; grp++){
        const int g0 = grp*32;

        // ---- gather 32 rows, split to packed bf16 planes ----
        for (int e = tid; e < 32*C1v; e += NT){
            int lr = e / C1v, q = e - lr*C1v;
            int r = g0 + lr;
            float4 v = PQ4[(size_t)nix[r]*C1v + q];
            const float* rs = &Rs[(r/K)*C1 + 4*q];
            unsigned hi0, lo0, hi1, lo1;
            split2(hi0, lo0, fmaxf(v.x - rs[0], 0.f), fmaxf(v.y - rs[1], 0.f));
            split2(hi1, lo1, fmaxf(v.z - rs[2], 0.f), fmaxf(v.w - rs[3], 0.f));
            int base = lr*P1 + 4*q;
            *reinterpret_cast<unsigned*>(&h1h[base])     = hi0;
            *reinterpret_cast<unsigned*>(&h1h[base + 2]) = hi1;
            *reinterpret_cast<unsigned*>(&h1l[base])     = lo0;
            *reinterpret_cast<unsigned*>(&h1l[base + 2]) = lo1;
        }
        __syncthreads();

        // ---- layer 2: two 16-row subtiles x NT2 col tiles over 8 warps ----
#pragma unroll 1
        for (int it = wid; it < 2*NT2; it += 8){
            int ms = it & 1, nt = it >> 1;
            int n0 = nt*8;
            float bb0 = b2s[n0 + 2*tig], bb1 = b2s[n0 + 2*tig + 1];
            float chh[4] = {bb0, bb1, bb0, bb1};
            float cx_[4] = {0.f, 0.f, 0.f, 0.f};
            const unsigned mso = 2u * (unsigned)(ms*16*P1);
#pragma unroll
            for (int kt = 0; kt < KT2; kt++){
                unsigned ah[4], al[4], bh[2], bl[2];
                ldsm4(ah, h1h_s + mso + lmb1 + 2u*(unsigned)(kt*16));
                ldsm4(al, h1l_s + mso + lmb1 + 2u*(unsigned)(kt*16));
                int wrow = (n0 + gid)*P1 + kt*16 + 2*tig;
                bh[0] = *reinterpret_cast<const unsigned*>(&w2h[wrow]);
                bh[1] = *reinterpret_cast<const unsigned*>(&w2h[wrow + 8]);
                bl[0] = *reinterpret_cast<const unsigned*>(&w2l[wrow]);
                bl[1] = *reinterpret_cast<const unsigned*>(&w2l[wrow + 8]);
                mma_bf16(chh, ah, bh);
                mma_bf16(cx_, al, bh);
                mma_bf16(cx_, ah, bl);
            }
            int c0 = n0 + 2*tig;
            int row0 = ms*16 + gid;
            unsigned hi, lo;
            split2(hi, lo, fmaxf(chh[0]+cx_[0], 0.f), fmaxf(chh[1]+cx_[1], 0.f));
            *reinterpret_cast<unsigned*>(&h2h[row0*P2 + c0]) = hi;
            *reinterpret_cast<unsigned*>(&h2l[row0*P2 + c0]) = lo;
            split2(hi, lo, fmaxf(chh[2]+cx_[2], 0.f), fmaxf(chh[3]+cx_[3], 0.f));
            *reinterpret_cast<unsigned*>(&h2h[(row0+8)*P2 + c0]) = hi;
            *reinterpret_cast<unsigned*>(&h2l[(row0+8)*P2 + c0]) = lo;
        }
        __syncthreads();

        // ---- layer 3 + maxpool ----
#pragma unroll 1
        for (int it = wid; it < 2*NT3; it += 8){
            int ms = it & 1, nt = it >> 1;
            int n0 = nt*8;
            const int cen = (g0 + ms*16) / K;
            float chh[4] = {0.f, 0.f, 0.f, 0.f};
            float cx_[4] = {0.f, 0.f, 0.f, 0.f};
            const unsigned mso = 2u * (unsigned)(ms*16*P2);
#pragma unroll
            for (int kt = 0; kt < KT3; kt++){
                unsigned ah[4], al[4], bh[2], bl[2];
                ldsm4(ah, h2h_s + mso + lmb2 + 2u*(unsigned)(kt*16));
                ldsm4(al, h2l_s + mso + lmb2 + 2u*(unsigned)(kt*16));
                int wrow = (n0 + gid)*P2 + kt*16 + 2*tig;
                bh[0] = *reinterpret_cast<const unsigned*>(&w3h[wrow]);
                bh[1] = *reinterpret_cast<const unsigned*>(&w3h[wrow + 8]);
                bl[0] = *reinterpret_cast<const unsigned*>(&w3l[wrow]);
                bl[1] = *reinterpret_cast<const unsigned*>(&w3l[wrow + 8]);
                mma_bf16(chh, ah, bh);
                mma_bf16(cx_, al, bh);
                mma_bf16(cx_, ah, bl);
            }
            float v0 = fmaxf(chh[0] + cx_[0], chh[2] + cx_[2]);
            float v1 = fmaxf(chh[1] + cx_[1], chh[3] + cx_[3]);
            v0 = fmaxf(v0, __shfl_xor_sync(0xFFFFFFFFu, v0, 4));
            v0 = fmaxf(v0, __shfl_xor_sync(0xFFFFFFFFu, v0, 8));
            v0 = fmaxf(v0, __shfl_xor_sync(0xFFFFFFFFu, v0, 16));
            v1 = fmaxf(v1, __shfl_xor_sync(0xFFFFFFFFu, v1, 4));
            v1 = fmaxf(v1, __shfl_xor_sync(0xFFFFFFFFu, v1, 8));
            v1 = fmaxf(v1, __shfl_xor_sync(0xFFFFFFFFu, v1, 16));
            if (gid == 0){
                int c0 = n0 + 2*tig;
                atomicMax(&mbuf[cen*C3 + c0],     __float_as_int(v0 + b3s[c0]));
                atomicMax(&mbuf[cen*C3 + c0 + 1], __float_as_int(v1 + b3s[c0 + 1]));
            }
        }
        __syncthreads();
    }

    for (int e = tid; e < BC*C3; e += NT){
        int c = e / C3, col = e - c*C3;
        out[(size_t)(bs0 + c)*320 + off + col] = __int_as_float(mbuf[e]);
    }
}

// smem bytes
template<int BC,int K,int C1,int C2,int C3>
constexpr int mma_smem(){
    constexpr int P1 = C1 + 8, P2 = C2 + 8;
    return 2*(2*C2*P1 + 2*C3*P2 + 2*32*P1 + 2*32*P2)
         + 4*(C2 + C3 + BC*C1) + 4*(BC*K + BC*C3);
}

// ---------------- launch ----------------
extern "C" void kernel_launch(void* const* d_in, const int* in_sizes, int n_in,
                              void* d_out, int out_size)
{
    const float* xyz  = (const float*)d_in[0];
    const float* feat = (const float*)d_in[1];
    const float* W[3][3]; const float* Bi[3][3];
    for (int i = 0; i < 3; i++)
        for (int j = 0; j < 3; j++){
            W[i][j]  = (const float*)d_in[2 + i*6 + j*2];
            Bi[i][j] = (const float*)d_in[3 + i*6 + j*2];
        }
    float* newxyz   = (float*)d_out;                 // (B, S, 3)
    float* feat_out = (float*)d_out + NB*NS*3;       // (B, S, 320)

    constexpr int SM0 = mma_smem<8,16,32,32,64>();    // ~30KB
    constexpr int SM1 = mma_smem<4,32,64,64,128>();   // ~78KB
    constexpr int SM2 = mma_smem<4,128,64,96,128>();  // ~109KB
    constexpr int SMF = 3*NP*4;

    cudaFuncSetAttribute((const void*)fps_kernel,
                         cudaFuncAttributeMaxDynamicSharedMemorySize, SMF);
    cudaFuncSetAttribute((const void*)mlp_kernel<0,8,16,32,32,64>,
                         cudaFuncAttributeMaxDynamicSharedMemorySize, SM0);
    cudaFuncSetAttribute((const void*)mlp_kernel<1,4,32,64,64,128>,
                         cudaFuncAttributeMaxDynamicSharedMemorySize, SM1);
    cudaFuncSetAttribute((const void*)mlp_kernel<2,4,128,64,96,128>,
                         cudaFuncAttributeMaxDynamicSharedMemorySize, SM2);

    wsplit_kernel<<<64, 256>>>(W[0][1], W[0][2], W[1][1], W[1][2], W[2][1], W[2][2]);
    fps_kernel<<<NB, 1024, SMF>>>(xyz, newxyz);
    pq_kernel<<<NB*NP/32, 160>>>(xyz, feat,
        W[0][0], Bi[0][0], W[1][0], Bi[1][0], W[2][0], Bi[2][0]);
    ball_kernel<<<NB*NS, 128>>>(xyz, newxyz);

    mlp_kernel<0,8,16,32,32,64><<<NB*NS/8, 256, SM0>>>(
        W[0][0], Bi[0][1], Bi[0][2], newxyz, feat_out, 0);
    mlp_kernel<1,4,32,64,64,128><<<NB*NS/4, 256, SM1>>>(
        W[1][0], Bi[1][1], Bi[1][2], newxyz, feat_out, 64);
    mlp_kernel<2,4,128,64,96,128><<<NB*NS/4, 256, SM2>>>(
        W[2][0], Bi[2][1], Bi[2][2], newxyz, feat_out, 192);
}